// round 7
// baseline (speedup 1.0000x reference)
#include <cuda_runtime.h>
#include <stdint.h>

// BitInput: out[i] = (u_i < p[i>>8]) ? 1.0f : 0.0f
// u_i = jax.random.uniform(key(42)), threefry_partitionable:
//   (b0,b1) = threefry2x32_20(key=(0,42), x0=0, x1=i); bits = b0^b1
//   u = (bits>>9) * 2^-23 exactly.  Integer compare: u < p <=> bits <u (p*2^23)<<9.
//
// Core identical to R4/R6 (6 IMAD-pair rotations in G2/G4, folded key
// injections, free first round, int-domain threshold).
// Single change vs R6: warp-coalesced store layout. Each warp owns 512
// consecutive elements; lane l handles elements 128h+4l+j (h=0..3, j=0..3),
// so every STG.128 is one contiguous 512B warp transaction (4 L1 wavefronts
// instead of ~16). The warp's two p values load as one aligned float2.

#define KS1 42u
#define KS2 0x1BD11BF0u

static __device__ __forceinline__ uint32_t rotl32(uint32_t x, int r) {
    return __funnelshift_l(x, x, r);
}

// mul-based rotate: (x*m) | umulhi(x,m)  (m = 1<<r), IMAD + IMAD.HI on fma pipe
#define MROT(x, m) ( ((x) * (m)) | __umulhi((x), (m)) )

static __device__ __forceinline__ uint32_t tf_bits(uint32_t i, uint32_t m29,
                                                   uint32_t m16, uint32_t m24)
{
    uint32_t x1 = i + KS1;     // lo32(counter) + ks1
    uint32_t x0 = x1;          // round-1 add with x0=0 is a copy

    // group 1: rotations 13,15,26,6
    x1 = rotl32(x1, 13) ^ x0;
    x0 += x1;  x1 = rotl32(x1, 15) ^ x0;
    x0 += x1;  x1 = rotl32(x1, 26) ^ x0;
    x0 += x1;  x1 = rotl32(x1,  6) ^ x0;
    // inject (ks1, ks2+1): x0 part folded into next round's IADD3
    x1 += KS2 + 1u;
    // group 2: rotations 17,29,16,24
    x0 = x0 + KS1 + x1;  x1 = rotl32(x1, 17) ^ x0;
    x0 += x1;  x1 = (MROT(x1, m29)) ^ x0;
    x0 += x1;  x1 = (MROT(x1, m16)) ^ x0;
    x0 += x1;  x1 = (MROT(x1, m24)) ^ x0;
    // inject (ks2, 2)
    x1 += 2u;
    // group 3: 13,15,26,6
    x0 = x0 + KS2 + x1;  x1 = rotl32(x1, 13) ^ x0;
    x0 += x1;  x1 = rotl32(x1, 15) ^ x0;
    x0 += x1;  x1 = rotl32(x1, 26) ^ x0;
    x0 += x1;  x1 = rotl32(x1,  6) ^ x0;
    // inject (0, ks1+3): x0 injection is zero
    x1 += KS1 + 3u;
    // group 4: 17,29,16,24
    x0 = x0 + x1;        x1 = rotl32(x1, 17) ^ x0;
    x0 += x1;  x1 = (MROT(x1, m29)) ^ x0;
    x0 += x1;  x1 = (MROT(x1, m16)) ^ x0;
    x0 += x1;  x1 = (MROT(x1, m24)) ^ x0;
    // inject (ks1, ks2+4)
    x1 += KS2 + 4u;
    // group 5: 13,15,26,6
    x0 = x0 + KS1 + x1;  x1 = rotl32(x1, 13) ^ x0;
    x0 += x1;  x1 = rotl32(x1, 15) ^ x0;
    x0 += x1;  x1 = rotl32(x1, 26) ^ x0;
    x0 += x1;  x1 = rotl32(x1,  6) ^ x0;
    // final inject (ks2, 5) + partitionable fold
    return (x0 + KS2) ^ (x1 + 5u);
}

__global__ void __launch_bounds__(256)
bitinput_kernel(const float2* __restrict__ prob2, uint4* __restrict__ out,
                uint32_t m29, uint32_t m16, uint32_t m24)
{
    const uint32_t t        = blockIdx.x * 256u + threadIdx.x;
    const uint32_t warp_id  = t >> 5;
    const uint32_t lane     = t & 31u;
    const uint32_t wbase    = warp_id << 9;          // 512 elements per warp
    const uint32_t wbase4   = warp_id << 7;          // uint4 index base

    // Two p-blocks per warp (elements [wbase, wbase+256) and [+256, +512)).
    // wbase>>8 = 2*warp_id is even -> one aligned float2 load, warp-uniform.
    const float2 pp = __ldg(&prob2[warp_id]);
    const uint32_t thr0 = ((uint32_t)(pp.x * 8388608.0f)) << 9;
    const uint32_t thr1 = ((uint32_t)(pp.y * 8388608.0f)) << 9;

#pragma unroll
    for (int h = 0; h < 4; ++h) {
        const uint32_t i0  = wbase + ((uint32_t)h << 7) + (lane << 2);
        const uint32_t thr = (h < 2) ? thr0 : thr1;
        uint32_t r[4];
#pragma unroll
        for (int j = 0; j < 4; ++j)
            r[j] = tf_bits(i0 + (uint32_t)j, m29, m16, m24);
        uint4 v;
        v.x = (r[0] < thr) ? 0x3f800000u : 0u;
        v.y = (r[1] < thr) ? 0x3f800000u : 0u;
        v.z = (r[2] < thr) ? 0x3f800000u : 0u;
        v.w = (r[3] < thr) ? 0x3f800000u : 0u;
        // coalesced: lanes 0..31 hit consecutive uint4 slots
        __stcs(&out[wbase4 + ((uint32_t)h << 5) + lane], v);
    }
}

extern "C" void kernel_launch(void* const* d_in, const int* in_sizes, int n_in,
                              void* d_out, int out_size)
{
    const float* prob = (const float*)d_in[0];
    const uint32_t n      = (uint32_t)out_size;   // 134,217,728
    const uint32_t nthr   = n >> 4;               // 16 outputs per thread
    const uint32_t blocks = nthr / 256u;

    bitinput_kernel<<<blocks, 256>>>((const float2*)prob, (uint4*)d_out,
                                     1u << 29, 1u << 16, 1u << 24);
}